// round 1
// baseline (speedup 1.0000x reference)
#include <cuda_runtime.h>
#include <cstdint>

#define NN 2048
#define LL 512
#define KK 16
#define DIMV 1024

// ---------------- scratch (static device memory; no allocs allowed) ----------
__device__ float g_R [NN * NN];
__device__ float g_RT[NN * NN];
__device__ float g_T1[NN * NN];
__device__ float g_AO[NN * NN];
__device__ float g_T2[NN * NN];
__device__ char  g_flags[NN];

// ---------------- f32x2 helpers ----------------------------------------------
__device__ __forceinline__ unsigned long long pack2(float a, float b) {
    unsigned long long r;
    asm("mov.b64 %0, {%1, %2};" : "=l"(r) : "f"(a), "f"(b));
    return r;
}
__device__ __forceinline__ void unpack2(unsigned long long v, float& a, float& b) {
    asm("mov.b64 {%0, %1}, %2;" : "=f"(a), "=f"(b) : "l"(v));
}
__device__ __forceinline__ unsigned long long fma2(unsigned long long a,
                                                   unsigned long long b,
                                                   unsigned long long c) {
    unsigned long long d;
    asm("fma.rn.f32x2 %0, %1, %2, %3;" : "=l"(d) : "l"(a), "l"(b), "l"(c));
    return d;
}

// ---------------- right scan: one CTA per 16-column tile ---------------------
// right starts as I; step l: right[idx_l, :] = O_l @ right[idx_l, :].
// Columns are independent -> each CTA owns 16 columns fully in smem.
__global__ void __launch_bounds__(256) k_right(const float* __restrict__ Og,
                                               const int* __restrict__ idxg) {
    extern __shared__ float sm[];
    float* Rt      = sm;                         // NN*KK floats (column tile)
    float* Os      = Rt + NN * KK;               // KK*KK floats
    int*   ids     = (int*)(Os + KK * KK);       // KK ints
    char*  touched = (char*)(ids + KK);          // NN bytes
    __shared__ int anyF;

    const int tid = threadIdx.x;
    const int c0  = blockIdx.x * KK;
    const int i   = tid >> 4;    // output row within the 16
    const int c   = tid & 15;    // column within tile

    for (int r = tid; r < NN; r += 256) {
#pragma unroll
        for (int cc = 0; cc < KK; cc++) Rt[r * KK + cc] = 0.0f;
        touched[r] = 0;
    }
    __syncthreads();
    if (tid < KK) {
        Rt[(c0 + tid) * KK + tid] = 1.0f;   // identity entries for our columns
        touched[c0 + tid] = 1;
    }
    __syncthreads();

    for (int l = 0; l < LL; l++) {
        if (tid < KK) ids[tid] = idxg[l * KK + tid];
        Os[tid] = Og[l * KK * KK + tid];     // 256 threads == KK*KK
        if (tid == 0) anyF = 0;
        __syncthreads();
        if (tid < KK && touched[ids[tid]]) anyF = 1;
        __syncthreads();
        if (anyF) {
            int   idr[KK];
            float orow[KK];
#pragma unroll
            for (int k = 0; k < KK; k++) {
                idr[k]  = ids[k];
                orow[k] = Os[i * KK + k];
            }
            float y = 0.0f;
#pragma unroll
            for (int k = 0; k < KK; k++) y += orow[k] * Rt[idr[k] * KK + c];
            __syncthreads();                 // all reads done before writes
            Rt[idr[i] * KK + c] = y;
            if (c == 0) touched[idr[i]] = 1;
            __syncthreads();
        }
    }

    // write tile to global right (row-major 2048x2048)
    for (int r = i; r < NN; r += 16)
        g_R[r * NN + c0 + c] = Rt[r * KK + c];
}

// ---------------- transpose g_R -> g_RT --------------------------------------
__global__ void k_transpose() {
    __shared__ float t[32][33];
    int x  = blockIdx.x * 32 + threadIdx.x;
    int y0 = blockIdx.y * 32 + threadIdx.y;
#pragma unroll
    for (int j = 0; j < 32; j += 8)
        t[threadIdx.y + j][threadIdx.x] = g_R[(y0 + j) * NN + x];
    __syncthreads();
    int x2 = blockIdx.y * 32 + threadIdx.x;
    int y2 = blockIdx.x * 32 + threadIdx.y;
#pragma unroll
    for (int j = 0; j < 32; j += 8)
        g_RT[(y2 + j) * NN + x2] = t[threadIdx.x][threadIdx.y + j];
}

// ---------------- fp32 GEMM, NN-layout, 128x128x16 tile, 8x8/thread, f32x2 ---
#define BM 128
#define BN 128
#define BK 16
#define ASTR (BM + 4)

__global__ void __launch_bounds__(256) k_gemm(const float* __restrict__ A,
                                              const float* __restrict__ B,
                                              float* __restrict__ C) {
    __shared__ float As[BK][ASTR];
    __shared__ float Bs[BK][BN];

    const int tid = threadIdx.x;
    const int bx = blockIdx.x, by = blockIdx.y;
    const int arow = tid >> 2;
    const int acol = (tid & 3) << 2;
    const int brow = tid >> 5;
    const int bcol = (tid & 31) << 2;
    const int ty = tid >> 4, tx = tid & 15;

    const float* Ap = A + (size_t)(by * BM + arow) * NN + acol;
    const float* Bp = B + (size_t)brow * NN + bx * BN + bcol;

    float4 a0 = *(const float4*)(Ap);
    float4 a1 = *(const float4*)(Ap + 64 * NN);
    float4 b0 = *(const float4*)(Bp);
    float4 b1 = *(const float4*)(Bp + 8 * NN);

    unsigned long long acc[8][4];
#pragma unroll
    for (int ii = 0; ii < 8; ii++)
#pragma unroll
        for (int jj = 0; jj < 4; jj++) acc[ii][jj] = 0ull;

    const int KT = NN / BK;
    for (int kt = 0; kt < KT; kt++) {
        As[acol + 0][arow]      = a0.x;
        As[acol + 1][arow]      = a0.y;
        As[acol + 2][arow]      = a0.z;
        As[acol + 3][arow]      = a0.w;
        As[acol + 0][arow + 64] = a1.x;
        As[acol + 1][arow + 64] = a1.y;
        As[acol + 2][arow + 64] = a1.z;
        As[acol + 3][arow + 64] = a1.w;
        *(float4*)&Bs[brow][bcol]     = b0;
        *(float4*)&Bs[brow + 8][bcol] = b1;
        __syncthreads();

        if (kt + 1 < KT) {
            a0 = *(const float4*)(Ap + (kt + 1) * BK);
            a1 = *(const float4*)(Ap + (kt + 1) * BK + 64 * NN);
            b0 = *(const float4*)(Bp + (size_t)(kt + 1) * BK * NN);
            b1 = *(const float4*)(Bp + (size_t)(kt + 1) * BK * NN + 8 * NN);
        }

#pragma unroll
        for (int kk = 0; kk < BK; kk++) {
            float4 av0 = *(const float4*)&As[kk][ty * 8];
            float4 av1 = *(const float4*)&As[kk][ty * 8 + 4];
            float4 bv0 = *(const float4*)&Bs[kk][tx * 8];
            float4 bv1 = *(const float4*)&Bs[kk][tx * 8 + 4];
            unsigned long long bp[4] = { pack2(bv0.x, bv0.y), pack2(bv0.z, bv0.w),
                                         pack2(bv1.x, bv1.y), pack2(bv1.z, bv1.w) };
            float ar[8] = { av0.x, av0.y, av0.z, av0.w, av1.x, av1.y, av1.z, av1.w };
#pragma unroll
            for (int ii = 0; ii < 8; ii++) {
                unsigned long long ad = pack2(ar[ii], ar[ii]);
#pragma unroll
                for (int jj = 0; jj < 4; jj++)
                    acc[ii][jj] = fma2(ad, bp[jj], acc[ii][jj]);
            }
        }
        __syncthreads();
    }

#pragma unroll
    for (int ii = 0; ii < 8; ii++) {
        int row = by * BM + ty * 8 + ii;
        float v[8];
#pragma unroll
        for (int jj = 0; jj < 4; jj++) unpack2(acc[ii][jj], v[2 * jj], v[2 * jj + 1]);
        float4* cp = (float4*)(C + (size_t)row * NN + bx * BN + tx * 8);
        cp[0] = make_float4(v[0], v[1], v[2], v[3]);
        cp[1] = make_float4(v[4], v[5], v[6], v[7]);
    }
}

// ---------------- flags / mask / gathers / copy -------------------------------
__global__ void k_flags(const int* __restrict__ act) {
    int t = threadIdx.x;
    g_flags[t] = 0;
    g_flags[t + 1024] = 0;
    __syncthreads();
    g_flags[act[t]] = 1;
}

__global__ void k_mask(float* __restrict__ Dout) {
    int j = blockIdx.x * 256 + threadIdx.x;
    int i = blockIdx.y;
    float v = g_AO[(size_t)i * NN + j];
    bool keep = (i == j) || (g_flags[i] && g_flags[j]);
    Dout[(size_t)i * NN + j] = keep ? v : 0.0f;
}

__global__ void k_gather_sq(const float* __restrict__ D, const int* __restrict__ sel,
                            float* __restrict__ out) {
    int b = blockIdx.x * 256 + threadIdx.x;   // 0..1023
    int a = blockIdx.y;                       // 0..1023
    int ra = sel[a], cb = sel[b];
    out[(size_t)a * DIMV + b] = D[(size_t)ra * NN + cb];
}

__global__ void k_gather_rows(const float* __restrict__ Rm, const int* __restrict__ sel,
                              float* __restrict__ out) {
    int c = blockIdx.x * 256 + threadIdx.x;   // 0..2047
    int a = blockIdx.y;                       // 0..1023
    out[(size_t)a * NN + c] = Rm[(size_t)sel[a] * NN + c];
}

__global__ void k_copy4(const float4* __restrict__ s, float4* __restrict__ d, int n4) {
    int t = blockIdx.x * 256 + threadIdx.x;
    if (t < n4) d[t] = s[t];
}

// ---------------- launch ------------------------------------------------------
extern "C" void kernel_launch(void* const* d_in, const int* in_sizes, int n_in,
                              void* d_out, int out_size) {
    const float* A    = (const float*)d_in[0];
    const float* O    = (const float*)d_in[1];
    const int*   idx  = (const int*)d_in[2];
    const int*   act  = (const int*)d_in[3];
    const int*   inact= (const int*)d_in[4];
    float* out = (float*)d_out;

    float *R, *RT, *T1, *AO, *T2;
    cudaGetSymbolAddress((void**)&R,  g_R);
    cudaGetSymbolAddress((void**)&RT, g_RT);
    cudaGetSymbolAddress((void**)&T1, g_T1);
    cudaGetSymbolAddress((void**)&AO, g_AO);
    cudaGetSymbolAddress((void**)&T2, g_T2);

    const size_t NN2 = (size_t)NN * NN;
    float* o_arec  = out;                       // A_rec           (2048x2048)
    float* o_right = out + NN2;                 // right           (2048x2048)
    float* o_D     = out + 2 * NN2;             // D               (2048x2048)
    float* o_mc    = out + 3 * NN2;             // mother coeffs   (1024x1024)
    float* o_fc    = o_mc + (size_t)DIMV * DIMV;// father coeffs   (1024x1024)
    float* o_mw    = o_fc + (size_t)DIMV * DIMV;// mother wavelets (1024x2048)
    float* o_fw    = o_mw + (size_t)DIMV * NN;  // father wavelets (1024x2048)

    const int smemR = NN * KK * 4 + KK * KK * 4 + KK * 4 + NN;  // 134208 B
    cudaFuncSetAttribute(k_right, cudaFuncAttributeMaxDynamicSharedMemorySize, smemR);

    k_flags<<<1, 1024>>>(act);
    k_right<<<NN / KK, 256, smemR>>>(O, idx);            // 128 CTAs
    k_transpose<<<dim3(64, 64), dim3(32, 8)>>>();
    k_copy4<<<(int)(NN2 / 4 / 256), 256>>>((const float4*)R, (float4*)o_right, (int)(NN2 / 4));

    dim3 gg(NN / BN, NN / BM);
    k_gemm<<<gg, 256>>>(R, A, T1);        // T1 = right @ A
    k_gemm<<<gg, 256>>>(T1, RT, AO);      // AO = T1 @ right^T
    k_mask<<<dim3(NN / 256, NN), 256>>>(o_D);
    k_gemm<<<gg, 256>>>(RT, o_D, T2);     // T2 = right^T @ D
    k_gemm<<<gg, 256>>>(T2, R, o_arec);   // A_rec = T2 @ right

    k_gather_sq<<<dim3(DIMV / 256, DIMV), 256>>>(o_D, inact, o_mc);
    k_gather_sq<<<dim3(DIMV / 256, DIMV), 256>>>(o_D, act,   o_fc);
    k_gather_rows<<<dim3(NN / 256, DIMV), 256>>>(R, inact, o_mw);
    k_gather_rows<<<dim3(NN / 256, DIMV), 256>>>(R, act,   o_fw);
}

// round 2
// speedup vs baseline: 1.3720x; 1.3720x over previous
#include <cuda_runtime.h>
#include <cstdint>

#define NN 2048
#define LL 512
#define KK 16
#define DIMV 1024

// ---------------- scratch (static device memory; no allocs allowed) ----------
__device__ float g_R [NN * NN];
__device__ float g_T1[NN * NN];
__device__ float g_T2[NN * NN];
__device__ float g_d [DIMV];

// ---------------- f32x2 helpers ----------------------------------------------
__device__ __forceinline__ unsigned long long pack2(float a, float b) {
    unsigned long long r;
    asm("mov.b64 %0, {%1, %2};" : "=l"(r) : "f"(a), "f"(b));
    return r;
}
__device__ __forceinline__ void unpack2(unsigned long long v, float& a, float& b) {
    asm("mov.b64 {%0, %1}, %2;" : "=f"(a), "=f"(b) : "l"(v));
}
__device__ __forceinline__ unsigned long long fma2(unsigned long long a,
                                                   unsigned long long b,
                                                   unsigned long long c) {
    unsigned long long d;
    asm("fma.rn.f32x2 %0, %1, %2, %3;" : "=l"(d) : "l"(a), "l"(b), "l"(c));
    return d;
}

// ---------------- right scan: one CTA per 16-column tile ---------------------
__global__ void __launch_bounds__(256) k_right(const float* __restrict__ Og,
                                               const int* __restrict__ idxg) {
    extern __shared__ float sm[];
    float* Rt      = sm;                         // NN*KK floats (column tile)
    float* Os      = Rt + NN * KK;               // KK*KK floats
    int*   ids     = (int*)(Os + KK * KK);       // KK ints
    char*  touched = (char*)(ids + KK);          // NN bytes
    __shared__ int anyF;

    const int tid = threadIdx.x;
    const int c0  = blockIdx.x * KK;
    const int i   = tid >> 4;    // output row within the 16
    const int c   = tid & 15;    // column within tile

    for (int r = tid; r < NN; r += 256) {
#pragma unroll
        for (int cc = 0; cc < KK; cc++) Rt[r * KK + cc] = 0.0f;
        touched[r] = 0;
    }
    __syncthreads();
    if (tid < KK) {
        Rt[(c0 + tid) * KK + tid] = 1.0f;
        touched[c0 + tid] = 1;
    }
    __syncthreads();

    for (int l = 0; l < LL; l++) {
        if (tid < KK) ids[tid] = idxg[l * KK + tid];
        Os[tid] = Og[l * KK * KK + tid];
        if (tid == 0) anyF = 0;
        __syncthreads();
        if (tid < KK && touched[ids[tid]]) anyF = 1;
        __syncthreads();
        if (anyF) {
            int   idr[KK];
            float orow[KK];
#pragma unroll
            for (int k = 0; k < KK; k++) {
                idr[k]  = ids[k];
                orow[k] = Os[i * KK + k];
            }
            float y = 0.0f;
#pragma unroll
            for (int k = 0; k < KK; k++) y += orow[k] * Rt[idr[k] * KK + c];
            __syncthreads();
            Rt[idr[i] * KK + c] = y;
            if (c == 0) touched[idr[i]] = 1;
            __syncthreads();
        }
    }

    for (int r = i; r < NN; r += 16)
        g_R[r * NN + c0 + c] = Rt[r * KK + c];
}

// ---------------- templated fp32 GEMM (NN / NT / TN), 128x128x16, f32x2 ------
#define BM 128
#define BN 128
#define BK 16
#define ASTR (BM + 4)

// MODE 0: C[M,N] = A[M,K]   @ B[K,N]
// MODE 1: C[M,N] = A[M,K]   @ B[N,K]^T
// MODE 2: C[M,N] = A[K,M]^T @ B[K,N]
template<int MODE>
__global__ void __launch_bounds__(256) k_gemm_t(const float* __restrict__ A,
                                                const float* __restrict__ B,
                                                float* __restrict__ C,
                                                int K, int lda, int ldb, int ldc) {
    __shared__ float As[BK][ASTR];
    __shared__ float Bs[BK][ASTR];

    const int tid = threadIdx.x;
    const int bx = blockIdx.x, by = blockIdx.y;
    const int r4  = tid >> 2;          // 0..63
    const int c4  = (tid & 3) << 2;    // 0,4,8,12
    const int r32 = tid >> 5;          // 0..7
    const int c32 = (tid & 31) << 2;   // 0..124
    const int ty = tid >> 4, tx = tid & 15;

    const float* Ap;
    const float* Bp;
    if (MODE == 2) Ap = A + (size_t)r32 * lda + by * BM + c32;          // A[K,M]
    else           Ap = A + (size_t)(by * BM + r4) * lda + c4;          // A[M,K]
    if (MODE == 1) Bp = B + (size_t)(bx * BN + r4) * ldb + c4;          // B[N,K]
    else           Bp = B + (size_t)r32 * ldb + bx * BN + c32;          // B[K,N]

    float4 a0, a1, b0, b1;

#define LOAD_A(kt)                                                              \
    if (MODE == 2) {                                                            \
        a0 = *(const float4*)(Ap + (size_t)(kt) * BK * lda);                    \
        a1 = *(const float4*)(Ap + (size_t)(kt) * BK * lda + 8 * (size_t)lda);  \
    } else {                                                                    \
        a0 = *(const float4*)(Ap + (kt) * BK);                                  \
        a1 = *(const float4*)(Ap + (kt) * BK + 64 * (size_t)lda);               \
    }
#define LOAD_B(kt)                                                              \
    if (MODE == 1) {                                                            \
        b0 = *(const float4*)(Bp + (kt) * BK);                                  \
        b1 = *(const float4*)(Bp + (kt) * BK + 64 * (size_t)ldb);               \
    } else {                                                                    \
        b0 = *(const float4*)(Bp + (size_t)(kt) * BK * ldb);                    \
        b1 = *(const float4*)(Bp + (size_t)(kt) * BK * ldb + 8 * (size_t)ldb);  \
    }

    LOAD_A(0);
    LOAD_B(0);

    unsigned long long acc[8][4];
#pragma unroll
    for (int ii = 0; ii < 8; ii++)
#pragma unroll
        for (int jj = 0; jj < 4; jj++) acc[ii][jj] = 0ull;

    const int KT = K / BK;
    for (int kt = 0; kt < KT; kt++) {
        if (MODE == 2) {
            *(float4*)&As[r32][c32]     = a0;
            *(float4*)&As[r32 + 8][c32] = a1;
        } else {
            As[c4 + 0][r4]      = a0.x;
            As[c4 + 1][r4]      = a0.y;
            As[c4 + 2][r4]      = a0.z;
            As[c4 + 3][r4]      = a0.w;
            As[c4 + 0][r4 + 64] = a1.x;
            As[c4 + 1][r4 + 64] = a1.y;
            As[c4 + 2][r4 + 64] = a1.z;
            As[c4 + 3][r4 + 64] = a1.w;
        }
        if (MODE == 1) {
            Bs[c4 + 0][r4]      = b0.x;
            Bs[c4 + 1][r4]      = b0.y;
            Bs[c4 + 2][r4]      = b0.z;
            Bs[c4 + 3][r4]      = b0.w;
            Bs[c4 + 0][r4 + 64] = b1.x;
            Bs[c4 + 1][r4 + 64] = b1.y;
            Bs[c4 + 2][r4 + 64] = b1.z;
            Bs[c4 + 3][r4 + 64] = b1.w;
        } else {
            *(float4*)&Bs[r32][c32]     = b0;
            *(float4*)&Bs[r32 + 8][c32] = b1;
        }
        __syncthreads();

        if (kt + 1 < KT) {
            LOAD_A(kt + 1);
            LOAD_B(kt + 1);
        }

#pragma unroll
        for (int kk = 0; kk < BK; kk++) {
            float4 av0 = *(const float4*)&As[kk][ty * 8];
            float4 av1 = *(const float4*)&As[kk][ty * 8 + 4];
            float4 bv0 = *(const float4*)&Bs[kk][tx * 8];
            float4 bv1 = *(const float4*)&Bs[kk][tx * 8 + 4];
            unsigned long long bp[4] = { pack2(bv0.x, bv0.y), pack2(bv0.z, bv0.w),
                                         pack2(bv1.x, bv1.y), pack2(bv1.z, bv1.w) };
            float ar[8] = { av0.x, av0.y, av0.z, av0.w, av1.x, av1.y, av1.z, av1.w };
#pragma unroll
            for (int ii = 0; ii < 8; ii++) {
                unsigned long long ad = pack2(ar[ii], ar[ii]);
#pragma unroll
                for (int jj = 0; jj < 4; jj++)
                    acc[ii][jj] = fma2(ad, bp[jj], acc[ii][jj]);
            }
        }
        __syncthreads();
    }
#undef LOAD_A
#undef LOAD_B

#pragma unroll
    for (int ii = 0; ii < 8; ii++) {
        int row = by * BM + ty * 8 + ii;
        float v[8];
#pragma unroll
        for (int jj = 0; jj < 4; jj++) unpack2(acc[ii][jj], v[2 * jj], v[2 * jj + 1]);
        float4* cp = (float4*)(C + (size_t)row * ldc + bx * BN + tx * 8);
        cp[0] = make_float4(v[0], v[1], v[2], v[3]);
        cp[1] = make_float4(v[4], v[5], v[6], v[7]);
    }
}

// ---------------- small kernels ------------------------------------------------
__global__ void k_copy4(const float4* __restrict__ s, float4* __restrict__ d, int n4) {
    int t = blockIdx.x * 256 + threadIdx.x;
    if (t < n4) d[t] = s[t];
}

__global__ void k_zero4(float4* __restrict__ p, int n4) {
    int t = blockIdx.x * 256 + threadIdx.x;
    if (t < n4) p[t] = make_float4(0.f, 0.f, 0.f, 0.f);
}

__global__ void k_gather_rows(const float* __restrict__ Rm, const int* __restrict__ sel,
                              float* __restrict__ out) {
    int c = blockIdx.x * 256 + threadIdx.x;   // 0..2047
    int a = blockIdx.y;                       // 0..1023
    out[(size_t)a * NN + c] = Rm[(size_t)sel[a] * NN + c];
}

// d[j] = dot(T1i[j,:], Mi[j,:])
__global__ void k_rowdot(const float* __restrict__ T1i, const float* __restrict__ Mi,
                         float* __restrict__ dvec) {
    __shared__ float red[256];
    int j = blockIdx.x;
    const float* a = T1i + (size_t)j * NN;
    const float* b = Mi  + (size_t)j * NN;
    float s = 0.f;
    for (int c = threadIdx.x; c < NN; c += 256) s += a[c] * b[c];
    red[threadIdx.x] = s;
    __syncthreads();
    for (int o = 128; o > 0; o >>= 1) {
        if (threadIdx.x < o) red[threadIdx.x] += red[threadIdx.x + o];
        __syncthreads();
    }
    if (threadIdx.x == 0) dvec[j] = red[0];
}

// Ms[j,:] = d[j] * Mi[j,:]
__global__ void k_scale_rows(const float* __restrict__ Mi, const float* __restrict__ dvec,
                             float* __restrict__ Ms) {
    int c = blockIdx.x * 256 + threadIdx.x;
    int j = blockIdx.y;
    Ms[(size_t)j * NN + c] = dvec[j] * Mi[(size_t)j * NN + c];
}

// D[act[a], act[b]] = Daa[a, b]
__global__ void k_scatter_aa(const float* __restrict__ Daa, const int* __restrict__ act,
                             float* __restrict__ Dout) {
    int b = blockIdx.x * 256 + threadIdx.x;
    int a = blockIdx.y;
    Dout[(size_t)act[a] * NN + act[b]] = Daa[(size_t)a * DIMV + b];
}

// D[g,g] = d[j] (g = inact[j]);  mc[j,j] = d[j]
__global__ void k_setdiag(const float* __restrict__ dvec, const int* __restrict__ inact,
                          float* __restrict__ Dout, float* __restrict__ mc) {
    int j = blockIdx.x * 256 + threadIdx.x;
    int g = inact[j];
    Dout[(size_t)g * NN + g] = dvec[j];
    mc[(size_t)j * DIMV + j] = dvec[j];
}

// ---------------- launch ------------------------------------------------------
extern "C" void kernel_launch(void* const* d_in, const int* in_sizes, int n_in,
                              void* d_out, int out_size) {
    const float* A    = (const float*)d_in[0];
    const float* O    = (const float*)d_in[1];
    const int*   idx  = (const int*)d_in[2];
    const int*   act  = (const int*)d_in[3];
    const int*   inact= (const int*)d_in[4];
    float* out = (float*)d_out;

    float *R, *T1, *T2, *dv;
    cudaGetSymbolAddress((void**)&R,  g_R);
    cudaGetSymbolAddress((void**)&T1, g_T1);
    cudaGetSymbolAddress((void**)&T2, g_T2);
    cudaGetSymbolAddress((void**)&dv, g_d);

    const size_t NN2 = (size_t)NN * NN;
    float* o_arec  = out;                        // A_rec           (2048x2048)
    float* o_right = out + NN2;                  // right           (2048x2048)
    float* o_D     = out + 2 * NN2;              // D               (2048x2048)
    float* o_mc    = out + 3 * NN2;               // mother coeffs   (1024x1024)
    float* o_fc    = o_mc + (size_t)DIMV * DIMV;  // father coeffs   (1024x1024)
    float* o_mw    = o_fc + (size_t)DIMV * DIMV;  // mother wavelets (1024x2048)
    float* o_fw    = o_mw + (size_t)DIMV * NN;    // father wavelets (1024x2048)
    // NOTE: W = [Mi; Fa] is contiguous at o_mw (2048 x 2048).

    const int smemR = NN * KK * 4 + KK * KK * 4 + KK * 4 + NN;
    cudaFuncSetAttribute(k_right, cudaFuncAttributeMaxDynamicSharedMemorySize, smemR);

    // 1. right scan
    k_right<<<NN / KK, 256, smemR>>>(O, idx);
    // 2. right output + gathered row blocks (also serve as GEMM operands)
    k_copy4<<<(int)(NN2 / 4 / 256), 256>>>((const float4*)R, (float4*)o_right, (int)(NN2 / 4));
    k_gather_rows<<<dim3(NN / 256, DIMV), 256>>>(R, inact, o_mw);   // Mi
    k_gather_rows<<<dim3(NN / 256, DIMV), 256>>>(R, act,   o_fw);   // Fa

    // 3. T1 = [Mi;Fa] @ A   (2048 x 2048 x 2048)
    k_gemm_t<0><<<dim3(NN / BN, NN / BM), 256>>>(o_mw, A, T1, NN, NN, NN, NN);

    // 4. father_coefficients = D_aa = T1a @ Fa^T   (1024 x 1024 x 2048)
    k_gemm_t<1><<<dim3(DIMV / BN, DIMV / BM), 256>>>(T1 + (size_t)DIMV * NN, o_fw, o_fc,
                                                     NN, NN, NN, DIMV);

    // 5. inactive diagonal d[j] = <T1i[j], Mi[j]>
    k_rowdot<<<DIMV, 256>>>(T1, o_mw, dv);

    // 6. U = D_aa @ Fa  -> T2 rows [1024:2048)   (1024 x 2048 x 1024)
    k_gemm_t<0><<<dim3(NN / BN, DIMV / BM), 256>>>(o_fc, o_fw, T2 + (size_t)DIMV * NN,
                                                   DIMV, DIMV, NN, NN);
    // 7. Ms = diag(d) @ Mi -> T2 rows [0:1024)
    k_scale_rows<<<dim3(NN / 256, DIMV), 256>>>(o_mw, dv, T2);

    // 8. A_rec = W^T @ [Ms; U]   (2048 x 2048 x 2048, TN)
    k_gemm_t<2><<<dim3(NN / BN, NN / BM), 256>>>(o_mw, T2, o_arec, NN, NN, NN, NN);

    // 9. D and mother_coefficients (zero + scatter)
    k_zero4<<<(int)(NN2 / 4 / 256), 256>>>((float4*)o_D, (int)(NN2 / 4));
    k_zero4<<<(int)((size_t)DIMV * DIMV / 4 / 256), 256>>>((float4*)o_mc,
                                                           (int)((size_t)DIMV * DIMV / 4));
    k_scatter_aa<<<dim3(DIMV / 256, DIMV), 256>>>(o_fc, act, o_D);
    k_setdiag<<<DIMV / 256, 256>>>(dv, inact, o_D, o_mc);
}

// round 4
// speedup vs baseline: 2.0327x; 1.4815x over previous
#include <cuda_runtime.h>
#include <cuda_bf16.h>
#include <cstdint>

#define NN 2048
#define LL 512
#define KK 16
#define DIMV 1024

typedef unsigned int u32;
typedef __nv_bfloat16 bf16;

// ---------------- scratch (static device memory; no allocs allowed) ----------
__device__ float g_R [NN * NN];
__device__ float g_T1[NN * NN];
__device__ float g_d [DIMV];
__device__ bf16 g_Ah [NN * NN],    g_Al [NN * NN];
__device__ bf16 g_Wh [NN * NN],    g_Wl [NN * NN];
__device__ bf16 g_T1ah[DIMV * NN], g_T1al[DIMV * NN];
__device__ bf16 g_Dh [DIMV * DIMV], g_Dl [DIMV * DIMV];
__device__ bf16 g_FTh[NN * DIMV],  g_FTl[NN * DIMV];
__device__ bf16 g_WTh[NN * NN],    g_WTl[NN * NN];
__device__ bf16 g_Bph[NN * NN],    g_Bpl[NN * NN];

__device__ __forceinline__ u32 smem_u32(const void* p) {
    u32 a;
    asm("{ .reg .u64 t; cvta.to.shared.u64 t, %1; cvt.u32.u64 %0, t; }" : "=r"(a) : "l"(p));
    return a;
}

// ---------------- right scan: one CTA per 16-column tile ---------------------
__global__ void __launch_bounds__(256) k_right(const float* __restrict__ Og,
                                               const int* __restrict__ idxg) {
    extern __shared__ float smf[];
    float* Rt      = smf;
    float* Os      = Rt + NN * KK;
    int*   ids     = (int*)(Os + KK * KK);
    char*  touched = (char*)(ids + KK);
    __shared__ int anyF;

    const int tid = threadIdx.x;
    const int c0  = blockIdx.x * KK;
    const int i   = tid >> 4;
    const int c   = tid & 15;

    for (int r = tid; r < NN; r += 256) {
#pragma unroll
        for (int cc = 0; cc < KK; cc++) Rt[r * KK + cc] = 0.0f;
        touched[r] = 0;
    }
    __syncthreads();
    if (tid < KK) {
        Rt[(c0 + tid) * KK + tid] = 1.0f;
        touched[c0 + tid] = 1;
    }
    __syncthreads();

    for (int l = 0; l < LL; l++) {
        if (tid < KK) ids[tid] = idxg[l * KK + tid];
        Os[tid] = Og[l * KK * KK + tid];
        if (tid == 0) anyF = 0;
        __syncthreads();
        if (tid < KK && touched[ids[tid]]) anyF = 1;
        __syncthreads();
        if (anyF) {
            int   idr[KK];
            float orow[KK];
#pragma unroll
            for (int k = 0; k < KK; k++) {
                idr[k]  = ids[k];
                orow[k] = Os[i * KK + k];
            }
            float y = 0.0f;
#pragma unroll
            for (int k = 0; k < KK; k++) y += orow[k] * Rt[idr[k] * KK + c];
            __syncthreads();
            Rt[idr[i] * KK + c] = y;
            if (c == 0) touched[idr[i]] = 1;
            __syncthreads();
        }
    }

    for (int r = i; r < NN; r += 16)
        g_R[r * NN + c0 + c] = Rt[r * KK + c];
}

// ---------------- mma.sync bf16x3 GEMM: C[m,n] = sum_k A[m,k]*B[n,k] ---------
// Tile 128x128, 256 threads (2x4 warps, each 64x32), K-chunk 32,
// double-buffered smem via cp.async. 80B smem pitch (conflict-free ldmatrix).
// EPI bits: 1 = write fp32 C, 2 = write bf16 hi/lo C, 4 = bf16 only rows>=1024.
#define PITCH 80
#define MATB  (128 * PITCH)
#define STAGE (4 * MATB)

__device__ __forceinline__ void mma_bf16(float* c, const u32* a, u32 b0, u32 b1) {
    asm volatile(
        "mma.sync.aligned.m16n8k16.row.col.f32.bf16.bf16.f32 "
        "{%0,%1,%2,%3}, {%4,%5,%6,%7}, {%8,%9}, {%0,%1,%2,%3};"
        : "+f"(c[0]), "+f"(c[1]), "+f"(c[2]), "+f"(c[3])
        : "r"(a[0]), "r"(a[1]), "r"(a[2]), "r"(a[3]), "r"(b0), "r"(b1));
}

template<int EPI>
__global__ __launch_bounds__(256, 1)
void k_mma(const bf16* __restrict__ Ah, const bf16* __restrict__ Al, int lda,
           const bf16* __restrict__ Bh, const bf16* __restrict__ Bl, int ldb,
           int K, float* __restrict__ Cf, int ldc,
           bf16* __restrict__ Ch, bf16* __restrict__ Cl, int ldch) {
    extern __shared__ char sm[];
    const u32 sbase = smem_u32(sm);

    const int tid  = threadIdx.x;
    const int lane = tid & 31, warp = tid >> 5;
    const int wm = warp >> 2, wn = warp & 3;
    const int bx = blockIdx.x, by = blockIdx.y;

    const int r0 = tid >> 2;            // 0..63
    const int sg = tid & 3;             // 16B segment within 64B K-chunk row

    const bf16* gA[2] = { Ah, Al };
    const bf16* gB[2] = { Bh, Bl };

    auto issue_stage = [&](int buf, int kt) {
        u32 s = sbase + buf * STAGE;
#pragma unroll
        for (int h = 0; h < 2; h++) {
#pragma unroll
            for (int rr = 0; rr < 2; rr++) {
                int r = r0 + rr * 64;
                const void* srcA = gA[h] + (size_t)(by * 128 + r) * lda + kt + sg * 8;
                u32 dstA = s + h * MATB + r * PITCH + sg * 16;
                asm volatile("cp.async.cg.shared.global [%0], [%1], 16;"
                             :: "r"(dstA), "l"(srcA));
                const void* srcB = gB[h] + (size_t)(bx * 128 + r) * ldb + kt + sg * 8;
                u32 dstB = s + (2 + h) * MATB + r * PITCH + sg * 16;
                asm volatile("cp.async.cg.shared.global [%0], [%1], 16;"
                             :: "r"(dstB), "l"(srcB));
            }
        }
        asm volatile("cp.async.commit_group;" ::: "memory");
    };

    float acc[4][4][4];
#pragma unroll
    for (int mt = 0; mt < 4; mt++)
#pragma unroll
        for (int nt = 0; nt < 4; nt++)
#pragma unroll
            for (int j = 0; j < 4; j++) acc[mt][nt][j] = 0.0f;

    issue_stage(0, 0);
    const int KT = K / 32;
    for (int c = 0; c < KT; c++) {
        if (c + 1 < KT) {
            issue_stage((c + 1) & 1, (c + 1) * 32);
            asm volatile("cp.async.wait_group 1;" ::: "memory");
        } else {
            asm volatile("cp.async.wait_group 0;" ::: "memory");
        }
        __syncthreads();
        const u32 s = sbase + (c & 1) * STAGE;

#pragma unroll
        for (int kh = 0; kh < 2; kh++) {
            const u32 lrow = (u32)(lane & 15) * PITCH + kh * 32 + (lane >> 4) * 16;
            u32 aF[2][4][4];
#pragma unroll
            for (int h = 0; h < 2; h++)
#pragma unroll
                for (int mt = 0; mt < 4; mt++) {
                    u32 ad = s + h * MATB + (u32)(wm * 64 + mt * 16) * PITCH + lrow;
                    asm volatile("ldmatrix.sync.aligned.m8n8.x4.shared.b16 "
                                 "{%0,%1,%2,%3}, [%4];"
                                 : "=r"(aF[h][mt][0]), "=r"(aF[h][mt][1]),
                                   "=r"(aF[h][mt][2]), "=r"(aF[h][mt][3]) : "r"(ad));
                }
            u32 bF[2][2][4];
#pragma unroll
            for (int h = 0; h < 2; h++)
#pragma unroll
                for (int np = 0; np < 2; np++) {
                    u32 ad = s + (2 + h) * MATB + (u32)(wn * 32 + np * 16) * PITCH + lrow;
                    asm volatile("ldmatrix.sync.aligned.m8n8.x4.shared.b16 "
                                 "{%0,%1,%2,%3}, [%4];"
                                 : "=r"(bF[h][np][0]), "=r"(bF[h][np][1]),
                                   "=r"(bF[h][np][2]), "=r"(bF[h][np][3]) : "r"(ad));
                }
#pragma unroll
            for (int mt = 0; mt < 4; mt++)
#pragma unroll
                for (int nt = 0; nt < 4; nt++) {
                    const int np = nt >> 1, sel = nt & 1;
                    u32 b0h = bF[0][np][sel], b1h = bF[0][np][sel + 2];
                    u32 b0l = bF[1][np][sel], b1l = bF[1][np][sel + 2];
                    mma_bf16(acc[mt][nt], aF[0][mt], b0h, b1h);
                    mma_bf16(acc[mt][nt], aF[0][mt], b0l, b1l);
                    mma_bf16(acc[mt][nt], aF[1][mt], b0h, b1h);
                }
        }
        __syncthreads();
    }

    // epilogue
    const int g = lane >> 2, tig = lane & 3;
#pragma unroll
    for (int mt = 0; mt < 4; mt++)
#pragma unroll
        for (int nt = 0; nt < 4; nt++)
#pragma unroll
            for (int hf = 0; hf < 2; hf++) {
                int row = by * 128 + wm * 64 + mt * 16 + g + hf * 8;
                int col = bx * 128 + wn * 32 + nt * 8 + tig * 2;
                float v0 = acc[mt][nt][hf * 2], v1 = acc[mt][nt][hf * 2 + 1];
                if (EPI & 1) {
                    float2* p = (float2*)(Cf + (size_t)row * ldc + col);
                    *p = make_float2(v0, v1);
                }
                if (EPI & 2) {
                    int br = row;
                    bool w = true;
                    if (EPI & 4) { w = (row >= DIMV); br = row - DIMV; }
                    if (w) {
                        bf16 h0 = __float2bfloat16(v0);
                        bf16 l0 = __float2bfloat16(v0 - __bfloat162float(h0));
                        bf16 h1 = __float2bfloat16(v1);
                        bf16 l1 = __float2bfloat16(v1 - __bfloat162float(h1));
                        *(__nv_bfloat162*)(Ch + (size_t)br * ldch + col) = __halves2bfloat162(h0, h1);
                        *(__nv_bfloat162*)(Cl + (size_t)br * ldch + col) = __halves2bfloat162(l0, l1);
                    }
                }
            }
}

// ---------------- conversions --------------------------------------------------
__global__ void k_conv(const float4* __restrict__ in, bf16* __restrict__ oh,
                       bf16* __restrict__ ol, int n4) {
    int t = blockIdx.x * 256 + threadIdx.x;
    if (t >= n4) return;
    float4 x = in[t];
    bf16 h0 = __float2bfloat16(x.x), h1 = __float2bfloat16(x.y);
    bf16 h2 = __float2bfloat16(x.z), h3 = __float2bfloat16(x.w);
    bf16 l0 = __float2bfloat16(x.x - __bfloat162float(h0));
    bf16 l1 = __float2bfloat16(x.y - __bfloat162float(h1));
    bf16 l2 = __float2bfloat16(x.z - __bfloat162float(h2));
    bf16 l3 = __float2bfloat16(x.w - __bfloat162float(h3));
    ((__nv_bfloat162*)oh)[2 * t]     = __halves2bfloat162(h0, h1);
    ((__nv_bfloat162*)oh)[2 * t + 1] = __halves2bfloat162(h2, h3);
    ((__nv_bfloat162*)ol)[2 * t]     = __halves2bfloat162(l0, l1);
    ((__nv_bfloat162*)ol)[2 * t + 1] = __halves2bfloat162(l2, l3);
}

// out[m][k] = (scale ? scale[k] : 1) * in[k][m]  (transpose-convert to bf16 hi/lo)
__global__ void k_tconv(const float* __restrict__ in, int ldi,
                        bf16* __restrict__ oh, bf16* __restrict__ ol,
                        int ldo, const float* __restrict__ scale) {
    __shared__ float t[32][33];
    int m0 = blockIdx.x * 32;
    int k0 = blockIdx.y * 32;
    int tx = threadIdx.x, ty = threadIdx.y;
#pragma unroll
    for (int j = 0; j < 32; j += 8)
        t[ty + j][tx] = in[(size_t)(k0 + ty + j) * ldi + m0 + tx];
    __syncthreads();
#pragma unroll
    for (int j = 0; j < 32; j += 8) {
        int m = m0 + ty + j, k = k0 + tx;
        float x = t[tx][ty + j];
        if (scale) x *= scale[k];
        bf16 h = __float2bfloat16(x);
        bf16 l = __float2bfloat16(x - __bfloat162float(h));
        oh[(size_t)m * ldo + k] = h;
        ol[(size_t)m * ldo + k] = l;
    }
}

// ---------------- small kernels ------------------------------------------------
__global__ void k_copy4(const float4* __restrict__ s, float4* __restrict__ d, int n4) {
    int t = blockIdx.x * 256 + threadIdx.x;
    if (t < n4) d[t] = s[t];
}

__global__ void k_zero4(float4* __restrict__ p, int n4) {
    int t = blockIdx.x * 256 + threadIdx.x;
    if (t < n4) p[t] = make_float4(0.f, 0.f, 0.f, 0.f);
}

__global__ void k_gather_rows(const float* __restrict__ Rm, const int* __restrict__ sel,
                              float* __restrict__ out) {
    int c = blockIdx.x * 256 + threadIdx.x;
    int a = blockIdx.y;
    out[(size_t)a * NN + c] = Rm[(size_t)sel[a] * NN + c];
}

__global__ void k_rowdot(const float* __restrict__ T1i, const float* __restrict__ Mi,
                         float* __restrict__ dvec) {
    __shared__ float red[256];
    int j = blockIdx.x;
    const float* a = T1i + (size_t)j * NN;
    const float* b = Mi  + (size_t)j * NN;
    float s = 0.f;
    for (int c = threadIdx.x; c < NN; c += 256) s += a[c] * b[c];
    red[threadIdx.x] = s;
    __syncthreads();
    for (int o = 128; o > 0; o >>= 1) {
        if (threadIdx.x < o) red[threadIdx.x] += red[threadIdx.x + o];
        __syncthreads();
    }
    if (threadIdx.x == 0) dvec[j] = red[0];
}

__global__ void k_scatter_aa(const float* __restrict__ Daa, const int* __restrict__ act,
                             float* __restrict__ Dout) {
    int b = blockIdx.x * 256 + threadIdx.x;
    int a = blockIdx.y;
    Dout[(size_t)act[a] * NN + act[b]] = Daa[(size_t)a * DIMV + b];
}

__global__ void k_setdiag(const float* __restrict__ dvec, const int* __restrict__ inact,
                          float* __restrict__ Dout, float* __restrict__ mc) {
    int j = blockIdx.x * 256 + threadIdx.x;
    int g = inact[j];
    Dout[(size_t)g * NN + g] = dvec[j];
    mc[(size_t)j * DIMV + j] = dvec[j];
}

// ---------------- launch ------------------------------------------------------
extern "C" void kernel_launch(void* const* d_in, const int* in_sizes, int n_in,
                              void* d_out, int out_size) {
    const float* A    = (const float*)d_in[0];
    const float* O    = (const float*)d_in[1];
    const int*   idx  = (const int*)d_in[2];
    const int*   act  = (const int*)d_in[3];
    const int*   inact= (const int*)d_in[4];
    float* out = (float*)d_out;

    float *R, *T1, *dv;
    bf16 *Ah, *Al, *Wh, *Wl, *T1ah, *T1al, *Dh, *Dl, *FTh, *FTl, *WTh, *WTl, *Bph, *Bpl;
    cudaGetSymbolAddress((void**)&R,   g_R);
    cudaGetSymbolAddress((void**)&T1,  g_T1);
    cudaGetSymbolAddress((void**)&dv,  g_d);
    cudaGetSymbolAddress((void**)&Ah,  g_Ah);   cudaGetSymbolAddress((void**)&Al,  g_Al);
    cudaGetSymbolAddress((void**)&Wh,  g_Wh);   cudaGetSymbolAddress((void**)&Wl,  g_Wl);
    cudaGetSymbolAddress((void**)&T1ah,g_T1ah); cudaGetSymbolAddress((void**)&T1al,g_T1al);
    cudaGetSymbolAddress((void**)&Dh,  g_Dh);   cudaGetSymbolAddress((void**)&Dl,  g_Dl);
    cudaGetSymbolAddress((void**)&FTh, g_FTh);  cudaGetSymbolAddress((void**)&FTl, g_FTl);
    cudaGetSymbolAddress((void**)&WTh, g_WTh);  cudaGetSymbolAddress((void**)&WTl, g_WTl);
    cudaGetSymbolAddress((void**)&Bph, g_Bph);  cudaGetSymbolAddress((void**)&Bpl, g_Bpl);

    const size_t NN2 = (size_t)NN * NN;
    float* o_arec  = out;
    float* o_right = out + NN2;
    float* o_D     = out + 2 * NN2;
    float* o_mc    = out + 3 * NN2;
    float* o_fc    = o_mc + (size_t)DIMV * DIMV;
    float* o_mw    = o_fc + (size_t)DIMV * DIMV;   // Mi (1024x2048); W = [Mi;Fa]
    float* o_fw    = o_mw + (size_t)DIMV * NN;     // Fa (1024x2048)

    const int smemR = NN * KK * 4 + KK * KK * 4 + KK * 4 + NN;
    cudaFuncSetAttribute(k_right, cudaFuncAttributeMaxDynamicSharedMemorySize, smemR);
    const int SMG = 2 * STAGE;   // 81920
    cudaFuncSetAttribute(k_mma<7>, cudaFuncAttributeMaxDynamicSharedMemorySize, SMG);
    cudaFuncSetAttribute(k_mma<3>, cudaFuncAttributeMaxDynamicSharedMemorySize, SMG);
    cudaFuncSetAttribute(k_mma<2>, cudaFuncAttributeMaxDynamicSharedMemorySize, SMG);
    cudaFuncSetAttribute(k_mma<1>, cudaFuncAttributeMaxDynamicSharedMemorySize, SMG);

    // 1. right scan + direct outputs
    k_right<<<NN / KK, 256, smemR>>>(O, idx);
    k_copy4<<<(int)(NN2 / 4 / 256), 256>>>((const float4*)R, (float4*)o_right, (int)(NN2 / 4));
    k_gather_rows<<<dim3(NN / 256, DIMV), 256>>>(R, inact, o_mw);   // Mi
    k_gather_rows<<<dim3(NN / 256, DIMV), 256>>>(R, act,   o_fw);   // Fa

    // 2. operand splits
    k_conv<<<(int)(NN2 / 4 / 256), 256>>>((const float4*)A,    Ah, Al, (int)(NN2 / 4));
    k_conv<<<(int)(NN2 / 4 / 256), 256>>>((const float4*)o_mw, Wh, Wl, (int)(NN2 / 4));

    // 3. T1 = W @ A  (A symmetric => NT with B=A); fp32 full + bf16 for rows>=1024
    k_mma<7><<<dim3(16, 16), 256, SMG>>>(Wh, Wl, NN, Ah, Al, NN, NN,
                                         T1, NN, T1ah, T1al, NN);
    // 4. d[j] = <T1i[j], Mi[j]>
    k_rowdot<<<DIMV, 256>>>(T1, o_mw, dv);

    // 5. father_coefficients = D_aa = T1a @ Fa^T  (fp32 -> o_fc, bf16 -> Dh/Dl)
    k_mma<3><<<dim3(8, 8), 256, SMG>>>(T1ah, T1al, NN,
                                       Wh + (size_t)DIMV * NN, Wl + (size_t)DIMV * NN, NN,
                                       NN, o_fc, DIMV, Dh, Dl, DIMV);

    // 6. FaT = Fa^T (2048x1024, bf16 split)
    k_tconv<<<dim3(NN / 32, DIMV / 32), dim3(32, 8)>>>(o_fw, NN, FTh, FTl, DIMV, nullptr);

    // 7. P = FaT @ D_aa (D_aa symmetric) -> B' right half (bf16 only)
    k_mma<2><<<dim3(8, 16), 256, SMG>>>(FTh, FTl, DIMV, Dh, Dl, DIMV, DIMV,
                                        nullptr, 0, Bph + DIMV, Bpl + DIMV, NN);

    // 8. B' left half: B'[n][k] = d[k] * Mi[k][n]
    k_tconv<<<dim3(NN / 32, DIMV / 32), dim3(32, 8)>>>(o_mw, NN, Bph, Bpl, NN, dv);

    // 9. WT = W^T (bf16 split)
    k_tconv<<<dim3(NN / 32, NN / 32), dim3(32, 8)>>>(o_mw, NN, WTh, WTl, NN, nullptr);

    // 10. A_rec = WT @ B'^T
    k_mma<1><<<dim3(16, 16), 256, SMG>>>(WTh, WTl, NN, Bph, Bpl, NN, NN,
                                         o_arec, NN, nullptr, nullptr, 0);

    // 11. D and mother_coefficients
    k_zero4<<<(int)(NN2 / 4 / 256), 256>>>((float4*)o_D, (int)(NN2 / 4));
    k_zero4<<<(int)((size_t)DIMV * DIMV / 4 / 256), 256>>>((float4*)o_mc,
                                                           (int)((size_t)DIMV * DIMV / 4));
    k_scatter_aa<<<dim3(DIMV / 256, DIMV), 256>>>(o_fc, act, o_D);
    k_setdiag<<<DIMV / 256, 256>>>(dv, inact, o_D, o_mc);
}

// round 5
// speedup vs baseline: 2.7846x; 1.3699x over previous
#include <cuda_runtime.h>
#include <cuda_bf16.h>
#include <cstdint>

#define NN 2048
#define LL 512
#define KK 16
#define DIMV 1024

typedef unsigned int u32;
typedef __nv_bfloat16 bf16;

// ---------------- scratch (static device memory; no allocs allowed) ----------
__device__ float g_R [NN * NN];
__device__ float g_d [DIMV];
__device__ float g_part[16 * DIMV];
__device__ int   g_winv[NN];
__device__ int   g_colmap[NN];
__device__ bf16 g_Ah [NN * NN],    g_Al [NN * NN];
__device__ bf16 g_Wh [NN * NN],    g_Wl [NN * NN];
__device__ bf16 g_T1ah[DIMV * NN], g_T1al[DIMV * NN];
__device__ bf16 g_Dh [DIMV * DIMV], g_Dl [DIMV * DIMV];
__device__ bf16 g_FTh[NN * DIMV],  g_FTl[NN * DIMV];
__device__ bf16 g_WTh[NN * NN],    g_WTl[NN * NN];
__device__ bf16 g_Bph[NN * NN],    g_Bpl[NN * NN];

__device__ __forceinline__ u32 smem_u32(const void* p) {
    u32 a;
    asm("{ .reg .u64 t; cvta.to.shared.u64 t, %1; cvt.u32.u64 %0, t; }" : "=r"(a) : "l"(p));
    return a;
}

__device__ __forceinline__ u32 split2(float x, float y, u32& lo) {
    bf16 hx = __float2bfloat16(x), hy = __float2bfloat16(y);
    bf16 lx = __float2bfloat16(x - __bfloat162float(hx));
    bf16 ly = __float2bfloat16(y - __bfloat162float(hy));
    __nv_bfloat162 l2 = __halves2bfloat162(lx, ly);
    lo = *(u32*)&l2;
    __nv_bfloat162 h2 = __halves2bfloat162(hx, hy);
    return *(u32*)&h2;
}

// ---------------- right scan v2: warp owns 2 columns, windowed staging -------
#define RWIN 8
__global__ void __launch_bounds__(256) k_right(const float* __restrict__ Og,
                                               const int* __restrict__ idxg) {
    extern __shared__ char smc[];
    float* Rt   = (float*)smc;                     // 8 slabs x NN x 2
    float* OsT  = Rt + 8 * NN * 2;                 // RWIN x 256 (transposed [k][i])
    int*   idsS = (int*)(OsT + RWIN * 256);        // RWIN x 16
    char*  tch  = (char*)(idsS + RWIN * 16);       // 8 x NN

    const int tid = threadIdx.x, lane = tid & 31, w = tid >> 5;
    const int c0 = blockIdx.x * KK;
    float* wr = Rt + w * (NN * 2);
    char*  wt = tch + w * NN;

    for (int r = lane; r < NN; r += 32) { wr[r * 2] = 0.f; wr[r * 2 + 1] = 0.f; wt[r] = 0; }
    __syncwarp();
    if (lane < 2) {
        int gc = c0 + w * 2 + lane;
        wr[gc * 2 + lane] = 1.0f;
        wt[gc] = 1;
    }

    const int i = lane >> 1, c = lane & 1;
    for (int w0 = 0; w0 < LL; w0 += RWIN) {
        __syncthreads();
#pragma unroll
        for (int s = 0; s < RWIN; s++) {
            int ii = tid >> 4, kk = tid & 15;
            OsT[s * 256 + kk * 16 + ii] = Og[(size_t)(w0 + s) * 256 + ii * 16 + kk];
        }
        if (tid < RWIN * 16) idsS[tid] = idxg[w0 * 16 + tid];
        __syncthreads();

        for (int s = 0; s < RWIN; s++) {
            const int* ids = idsS + s * 16;
            const float* Ot = OsT + s * 256;
            int myid = ids[lane & 15];
            bool hit = (lane < 16) && wt[myid];
            if (!__ballot_sync(0xffffffffu, hit)) continue;
            float y = 0.f;
#pragma unroll
            for (int k = 0; k < KK; k++)
                y += Ot[k * 16 + i] * wr[ids[k] * 2 + c];
            __syncwarp();
            int ri = ids[i];
            wr[ri * 2 + c] = y;
            if (c == 0) wt[ri] = 1;
            __syncwarp();
        }
    }
    __syncthreads();
    {
        int cc = tid & 15;
        const float* slab = Rt + (cc >> 1) * (NN * 2);
        int sc = cc & 1;
        for (int r = tid >> 4; r < NN; r += 16)
            g_R[(size_t)r * NN + c0 + cc] = slab[r * 2 + sc];
    }
}

// ---------------- mma.sync bf16x3 GEMM: C[m,n] = sum_k A[m,k]*B[n,k] ---------
// 128x128 tile, 256 threads (2x4 warps, 64x32 each), K-chunk 32, 3-stage cp.async.
// EPI bits: 1=fp32 C, 2=bf16 hi/lo C, 4=bf16 only rows>=1024, 8=rowdot rows<1024.
#define PITCH 80
#define MATB  (128 * PITCH)
#define STAGE (4 * MATB)
#define SMG   (3 * STAGE + 2048)

__device__ __forceinline__ void mma_bf16(float* c, const u32* a, u32 b0, u32 b1) {
    asm volatile(
        "mma.sync.aligned.m16n8k16.row.col.f32.bf16.bf16.f32 "
        "{%0,%1,%2,%3}, {%4,%5,%6,%7}, {%8,%9}, {%0,%1,%2,%3};"
        : "+f"(c[0]), "+f"(c[1]), "+f"(c[2]), "+f"(c[3])
        : "r"(a[0]), "r"(a[1]), "r"(a[2]), "r"(a[3]), "r"(b0), "r"(b1));
}

template<int EPI>
__global__ __launch_bounds__(256, 1)
void k_mma(const bf16* __restrict__ Ah, const bf16* __restrict__ Al, int lda,
           const bf16* __restrict__ Bh, const bf16* __restrict__ Bl, int ldb,
           int K, float* __restrict__ Cf, int ldc,
           bf16* __restrict__ Ch, bf16* __restrict__ Cl, int ldch,
           const float* __restrict__ Wf, float* __restrict__ gpart) {
    extern __shared__ char sm[];
    const u32 sbase = smem_u32(sm);

    const int tid  = threadIdx.x;
    const int lane = tid & 31, warp = tid >> 5;
    const int wm = warp >> 2, wn = warp & 3;
    const int bx = blockIdx.x, by = blockIdx.y;

    const int r0 = tid >> 2;
    const int sg = tid & 3;

    const bf16* gA[2] = { Ah, Al };
    const bf16* gB[2] = { Bh, Bl };

    auto issue_stage = [&](int buf, int kt) {
        u32 s = sbase + buf * STAGE;
#pragma unroll
        for (int h = 0; h < 2; h++) {
#pragma unroll
            for (int rr = 0; rr < 2; rr++) {
                int r = r0 + rr * 64;
                const void* srcA = gA[h] + (size_t)(by * 128 + r) * lda + kt + sg * 8;
                u32 dstA = s + h * MATB + r * PITCH + sg * 16;
                asm volatile("cp.async.cg.shared.global [%0], [%1], 16;"
                             :: "r"(dstA), "l"(srcA));
                const void* srcB = gB[h] + (size_t)(bx * 128 + r) * ldb + kt + sg * 8;
                u32 dstB = s + (2 + h) * MATB + r * PITCH + sg * 16;
                asm volatile("cp.async.cg.shared.global [%0], [%1], 16;"
                             :: "r"(dstB), "l"(srcB));
            }
        }
        asm volatile("cp.async.commit_group;" ::: "memory");
    };

    float acc[4][4][4];
#pragma unroll
    for (int mt = 0; mt < 4; mt++)
#pragma unroll
        for (int nt = 0; nt < 4; nt++)
#pragma unroll
            for (int j = 0; j < 4; j++) acc[mt][nt][j] = 0.0f;

    const int KT = K / 32;
    issue_stage(0, 0);
    issue_stage(1, 32);

    for (int c = 0; c < KT; c++) {
        if (c + 1 < KT) asm volatile("cp.async.wait_group 1;" ::: "memory");
        else            asm volatile("cp.async.wait_group 0;" ::: "memory");
        __syncthreads();
        if (c + 2 < KT) issue_stage((c + 2) % 3, (c + 2) * 32);
        const u32 s = sbase + (c % 3) * STAGE;

#pragma unroll
        for (int kh = 0; kh < 2; kh++) {
            const u32 lrow = (u32)(lane & 15) * PITCH + kh * 32 + (lane >> 4) * 16;
            u32 aF[2][4][4];
#pragma unroll
            for (int h = 0; h < 2; h++)
#pragma unroll
                for (int mt = 0; mt < 4; mt++) {
                    u32 ad = s + h * MATB + (u32)(wm * 64 + mt * 16) * PITCH + lrow;
                    asm volatile("ldmatrix.sync.aligned.m8n8.x4.shared.b16 "
                                 "{%0,%1,%2,%3}, [%4];"
                                 : "=r"(aF[h][mt][0]), "=r"(aF[h][mt][1]),
                                   "=r"(aF[h][mt][2]), "=r"(aF[h][mt][3]) : "r"(ad));
                }
            u32 bF[2][2][4];
#pragma unroll
            for (int h = 0; h < 2; h++)
#pragma unroll
                for (int np = 0; np < 2; np++) {
                    u32 ad = s + (2 + h) * MATB + (u32)(wn * 32 + np * 16) * PITCH + lrow;
                    asm volatile("ldmatrix.sync.aligned.m8n8.x4.shared.b16 "
                                 "{%0,%1,%2,%3}, [%4];"
                                 : "=r"(bF[h][np][0]), "=r"(bF[h][np][1]),
                                   "=r"(bF[h][np][2]), "=r"(bF[h][np][3]) : "r"(ad));
                }
#pragma unroll
            for (int mt = 0; mt < 4; mt++)
#pragma unroll
                for (int nt = 0; nt < 4; nt++) {
                    const int np = nt >> 1, sel = nt & 1;
                    u32 b0h = bF[0][np][sel], b1h = bF[0][np][sel + 2];
                    u32 b0l = bF[1][np][sel], b1l = bF[1][np][sel + 2];
                    mma_bf16(acc[mt][nt], aF[0][mt], b0h, b1h);
                    mma_bf16(acc[mt][nt], aF[0][mt], b0l, b1l);
                    mma_bf16(acc[mt][nt], aF[1][mt], b0h, b1h);
                }
        }
    }

    // ---------------- epilogue ----------------
    const int g = lane >> 2, tig = lane & 3;
    const bool dot = (EPI & 8) && (by < 8);

    if (!dot) {
#pragma unroll
        for (int mt = 0; mt < 4; mt++)
#pragma unroll
            for (int nt = 0; nt < 4; nt++)
#pragma unroll
                for (int hf = 0; hf < 2; hf++) {
                    int row = by * 128 + wm * 64 + mt * 16 + g + hf * 8;
                    int col = bx * 128 + wn * 32 + nt * 8 + tig * 2;
                    float v0 = acc[mt][nt][hf * 2], v1 = acc[mt][nt][hf * 2 + 1];
                    if (EPI & 1) {
                        float2* p = (float2*)(Cf + (size_t)row * ldc + col);
                        *p = make_float2(v0, v1);
                    }
                    if (EPI & 2) {
                        int br = row;
                        bool wv = true;
                        if (EPI & 4) { wv = (row >= DIMV); br = row - DIMV; }
                        if (wv) {
                            u32 lo, hi = split2(v0, v1, lo);
                            *(u32*)(Ch + (size_t)br * ldch + col) = hi;
                            *(u32*)(Cl + (size_t)br * ldch + col) = lo;
                        }
                    }
                }
    } else {
        // d-partials: rp[mt*2+hf] = sum over this thread's cols of T1*W
        float rp[8];
#pragma unroll
        for (int q = 0; q < 8; q++) rp[q] = 0.f;
#pragma unroll
        for (int mt = 0; mt < 4; mt++)
#pragma unroll
            for (int hf = 0; hf < 2; hf++) {
                int row = by * 128 + wm * 64 + mt * 16 + g + hf * 8;
                const float* wrow = Wf + (size_t)row * NN;
#pragma unroll
                for (int nt = 0; nt < 4; nt++) {
                    int col = bx * 128 + wn * 32 + nt * 8 + tig * 2;
                    float2 wv = *(const float2*)(wrow + col);
                    rp[mt * 2 + hf] += acc[mt][nt][hf * 2] * wv.x
                                     + acc[mt][nt][hf * 2 + 1] * wv.y;
                }
            }
#pragma unroll
        for (int o = 1; o <= 2; o <<= 1)
#pragma unroll
            for (int q = 0; q < 8; q++)
                rp[q] += __shfl_xor_sync(0xffffffffu, rp[q], o);
        float* sred = (float*)(sm + 3 * STAGE);   // [128][4]
        __syncthreads();
        if (tig == 0) {
#pragma unroll
            for (int mt = 0; mt < 4; mt++)
#pragma unroll
                for (int hf = 0; hf < 2; hf++) {
                    int rl = wm * 64 + mt * 16 + hf * 8 + g;
                    sred[rl * 4 + wn] = rp[mt * 2 + hf];
                }
        }
        __syncthreads();
        if (tid < 128) {
            float s2 = sred[tid * 4] + sred[tid * 4 + 1] + sred[tid * 4 + 2] + sred[tid * 4 + 3];
            gpart[bx * DIMV + by * 128 + tid] = s2;
        }
    }
}

// ---------------- fused prep: R row -> right, W fp32 (perm), Wh, Wl ----------
__global__ void __launch_bounds__(256) k_prep(const float* __restrict__ R,
                                              const int* __restrict__ winv,
                                              float* __restrict__ o_right,
                                              float* __restrict__ Wf,
                                              bf16* __restrict__ Wh,
                                              bf16* __restrict__ Wl) {
    int r = blockIdx.x, t = threadIdx.x;
    int p = winv[r];
    const float4* src = (const float4*)(R + (size_t)r * NN);
    float4* dr = (float4*)(o_right + (size_t)r * NN);
    float4* dw = (float4*)(Wf + (size_t)p * NN);
    uint2*  dh = (uint2*)(Wh + (size_t)p * NN);
    uint2*  dl = (uint2*)(Wl + (size_t)p * NN);
#pragma unroll
    for (int j = 0; j < 2; j++) {
        int k = t + j * 256;
        float4 v = src[k];
        dr[k] = v;
        dw[k] = v;
        u32 lo0, lo1;
        u32 hi0 = split2(v.x, v.y, lo0);
        u32 hi1 = split2(v.z, v.w, lo1);
        dh[k] = make_uint2(hi0, hi1);
        dl[k] = make_uint2(lo0, lo1);
    }
}

// ---------------- conv A -> bf16 hi/lo (8 elems/thread) -----------------------
__global__ void k_conv(const float* __restrict__ in, bf16* __restrict__ oh,
                       bf16* __restrict__ ol, int n8) {
    int t = blockIdx.x * 256 + threadIdx.x;
    if (t >= n8) return;
    float4 a = ((const float4*)in)[2 * t], b = ((const float4*)in)[2 * t + 1];
    u32 l0, l1, l2, l3;
    u32 h0 = split2(a.x, a.y, l0);
    u32 h1 = split2(a.z, a.w, l1);
    u32 h2 = split2(b.x, b.y, l2);
    u32 h3 = split2(b.z, b.w, l3);
    ((uint4*)oh)[t] = make_uint4(h0, h1, h2, h3);
    ((uint4*)ol)[t] = make_uint4(l0, l1, l2, l3);
}

// ---------------- bf16 hi/lo pair transpose: out[m][k] = in[k][m] -------------
__global__ void k_tbf(const bf16* __restrict__ ih, const bf16* __restrict__ il, int ldin,
                      bf16* __restrict__ oh, bf16* __restrict__ ol, int ldout) {
    __shared__ u32 th[64][33], tl[64][33];
    int k0 = blockIdx.x * 64, m0 = blockIdx.y * 64;
    int t = threadIdx.x;
#pragma unroll
    for (int j = 0; j < 8; j++) {
        int idx = t + j * 256;
        int kr = idx >> 5, mu = idx & 31;
        th[kr][mu] = *(const u32*)&ih[(size_t)(k0 + kr) * ldin + m0 + 2 * mu];
        tl[kr][mu] = *(const u32*)&il[(size_t)(k0 + kr) * ldin + m0 + 2 * mu];
    }
    __syncthreads();
#pragma unroll
    for (int j = 0; j < 8; j++) {
        int idx = t + j * 256;
        int mr = idx >> 5, ku = idx & 31;
        u32 u0 = th[2 * ku][mr >> 1], u1 = th[2 * ku + 1][mr >> 1];
        u32 v0 = tl[2 * ku][mr >> 1], v1 = tl[2 * ku + 1][mr >> 1];
        u32 sel = (mr & 1) ? 0x7632 : 0x5410;
        *(u32*)&oh[(size_t)(m0 + mr) * ldout + k0 + 2 * ku] = __byte_perm(u0, u1, sel);
        *(u32*)&ol[(size_t)(m0 + mr) * ldout + k0 + 2 * ku] = __byte_perm(v0, v1, sel);
    }
}

// ---------------- Bp left: Bp[n][k] = d[k] * R[inact[k]][n], bf16 split -------
__global__ void k_bpl(const float* __restrict__ R, const int* __restrict__ inact,
                      const float* __restrict__ dvec,
                      bf16* __restrict__ oh, bf16* __restrict__ ol) {
    __shared__ float tf[32][65];
    int k0 = blockIdx.x * 32, n0 = blockIdx.y * 64;
    int t = threadIdx.x;
#pragma unroll
    for (int j = 0; j < 8; j++) {
        int idx = t + j * 256;
        int kr = idx >> 6, nc = idx & 63;
        tf[kr][nc] = dvec[k0 + kr] * R[(size_t)inact[k0 + kr] * NN + n0 + nc];
    }
    __syncthreads();
#pragma unroll
    for (int j = 0; j < 4; j++) {
        int idx = t + j * 256;
        int nr = idx >> 4, ku = idx & 15;
        float v0 = tf[2 * ku][nr], v1 = tf[2 * ku + 1][nr];
        u32 lo, hi = split2(v0, v1, lo);
        *(u32*)&oh[(size_t)(n0 + nr) * NN + k0 + 2 * ku] = hi;
        *(u32*)&ol[(size_t)(n0 + nr) * NN + k0 + 2 * ku] = lo;
    }
}

// ---------------- maps / reductions / outputs ---------------------------------
__global__ void k_maps0(int* colmap) {
    int t = blockIdx.x * 256 + threadIdx.x;
    colmap[t] = -1;
}
__global__ void k_maps1(const int* __restrict__ act, const int* __restrict__ inact,
                        int* winv, int* colmap) {
    int t = blockIdx.x * 256 + threadIdx.x;   // 0..1023
    winv[inact[t]] = t;
    winv[act[t]]   = DIMV + t;
    colmap[act[t]] = t;
}

__global__ void k_dred(const float* __restrict__ gpart, float* __restrict__ dvec) {
    int j = blockIdx.x * 256 + threadIdx.x;
    float s = 0.f;
#pragma unroll
    for (int b = 0; b < 16; b++) s += gpart[b * DIMV + j];
    dvec[j] = s;
}

__global__ void __launch_bounds__(256) k_dfill(const float* __restrict__ Daa,
                                               const int* __restrict__ colmap,
                                               const int* __restrict__ winv,
                                               const float* __restrict__ dvec,
                                               float* __restrict__ D) {
    int gr = blockIdx.x, t = threadIdx.x;
    int a = colmap[gr];
    float* row = D + (size_t)gr * NN;
    if (a < 0) {
        float4 z = make_float4(0.f, 0.f, 0.f, 0.f);
#pragma unroll
        for (int j = 0; j < 2; j++) ((float4*)row)[t + j * 256] = z;
        __syncthreads();
        if (t == 0) row[gr] = dvec[winv[gr]];
    } else {
        const float* dr = Daa + (size_t)a * DIMV;
#pragma unroll
        for (int j = 0; j < 8; j++) {
            int cc = t + j * 256;
            int cm = colmap[cc];
            row[cc] = (cm >= 0) ? dr[cm] : 0.f;
        }
    }
}

__global__ void k_mc(const float* __restrict__ dvec, float* __restrict__ mc) {
    int j = blockIdx.x, t = threadIdx.x;
    float* row = mc + (size_t)j * DIMV;
    ((float4*)row)[t] = make_float4(0.f, 0.f, 0.f, 0.f);
    __syncthreads();
    if (t == 0) row[j] = dvec[j];
}

// ---------------- launch ------------------------------------------------------
extern "C" void kernel_launch(void* const* d_in, const int* in_sizes, int n_in,
                              void* d_out, int out_size) {
    const float* A    = (const float*)d_in[0];
    const float* O    = (const float*)d_in[1];
    const int*   idx  = (const int*)d_in[2];
    const int*   act  = (const int*)d_in[3];
    const int*   inact= (const int*)d_in[4];
    float* out = (float*)d_out;

    float *R, *dv, *gpart;
    int *winv, *colmap;
    bf16 *Ah, *Al, *Wh, *Wl, *T1ah, *T1al, *Dh, *Dl, *FTh, *FTl, *WTh, *WTl, *Bph, *Bpl;
    cudaGetSymbolAddress((void**)&R,     g_R);
    cudaGetSymbolAddress((void**)&dv,    g_d);
    cudaGetSymbolAddress((void**)&gpart, g_part);
    cudaGetSymbolAddress((void**)&winv,  g_winv);
    cudaGetSymbolAddress((void**)&colmap,g_colmap);
    cudaGetSymbolAddress((void**)&Ah,  g_Ah);   cudaGetSymbolAddress((void**)&Al,  g_Al);
    cudaGetSymbolAddress((void**)&Wh,  g_Wh);   cudaGetSymbolAddress((void**)&Wl,  g_Wl);
    cudaGetSymbolAddress((void**)&T1ah,g_T1ah); cudaGetSymbolAddress((void**)&T1al,g_T1al);
    cudaGetSymbolAddress((void**)&Dh,  g_Dh);   cudaGetSymbolAddress((void**)&Dl,  g_Dl);
    cudaGetSymbolAddress((void**)&FTh, g_FTh);  cudaGetSymbolAddress((void**)&FTl, g_FTl);
    cudaGetSymbolAddress((void**)&WTh, g_WTh);  cudaGetSymbolAddress((void**)&WTl, g_WTl);
    cudaGetSymbolAddress((void**)&Bph, g_Bph);  cudaGetSymbolAddress((void**)&Bpl, g_Bpl);

    const size_t NN2 = (size_t)NN * NN;
    float* o_arec  = out;
    float* o_right = out + NN2;
    float* o_D     = out + 2 * NN2;
    float* o_mc    = out + 3 * NN2;
    float* o_fc    = o_mc + (size_t)DIMV * DIMV;
    float* o_mw    = o_fc + (size_t)DIMV * DIMV;   // W fp32 = [Mi;Fa] contiguous
    // o_fw = o_mw + DIMV*NN (contiguous continuation)

    const int smemR = 8 * NN * 2 * 4 + RWIN * 256 * 4 + RWIN * 16 * 4 + 8 * NN;
    cudaFuncSetAttribute(k_right, cudaFuncAttributeMaxDynamicSharedMemorySize, smemR);
    cudaFuncSetAttribute(k_mma<14>, cudaFuncAttributeMaxDynamicSharedMemorySize, SMG);
    cudaFuncSetAttribute(k_mma<3>,  cudaFuncAttributeMaxDynamicSharedMemorySize, SMG);
    cudaFuncSetAttribute(k_mma<2>,  cudaFuncAttributeMaxDynamicSharedMemorySize, SMG);
    cudaFuncSetAttribute(k_mma<1>,  cudaFuncAttributeMaxDynamicSharedMemorySize, SMG);

    // 1. maps + A split (independent of scan)
    k_maps0<<<NN / 256, 256>>>(colmap);
    k_maps1<<<DIMV / 256, 256>>>(act, inact, winv, colmap);
    k_conv<<<(int)(NN2 / 8 / 256), 256>>>(A, Ah, Al, (int)(NN2 / 8));

    // 2. right scan + fused prep (right output, W fp32, Wh/Wl)
    k_right<<<NN / KK, 256, smemR>>>(O, idx);
    k_prep<<<NN, 256>>>(R, winv, o_right, o_mw, Wh, Wl);

    // 3. T1 = W @ A (A sym, NT). rows<1024: fused rowdot partials; rows>=1024: bf16 T1a
    k_mma<14><<<dim3(16, 16), 256, SMG>>>(Wh, Wl, NN, Ah, Al, NN, NN,
                                          nullptr, 0, T1ah, T1al, NN, o_mw, gpart);
    k_dred<<<DIMV / 256, 256>>>(gpart, dv);

    // 4. father_coefficients = D_aa = T1a @ Fa^T (fp32 -> o_fc, bf16 -> Dh/Dl)
    k_mma<3><<<dim3(8, 8), 256, SMG>>>(T1ah, T1al, NN,
                                       Wh + (size_t)DIMV * NN, Wl + (size_t)DIMV * NN, NN,
                                       NN, o_fc, DIMV, Dh, Dl, DIMV, nullptr, nullptr);

    // 5. FaT = Fa^T (bf16-domain transpose)
    k_tbf<<<dim3(DIMV / 64, NN / 64), 256>>>(Wh + (size_t)DIMV * NN, Wl + (size_t)DIMV * NN,
                                             NN, FTh, FTl, DIMV);

    // 6. P = FaT @ D_aa (D_aa sym) -> B' right half (bf16)
    k_mma<2><<<dim3(8, 16), 256, SMG>>>(FTh, FTl, DIMV, Dh, Dl, DIMV, DIMV,
                                        nullptr, 0, Bph + DIMV, Bpl + DIMV, NN,
                                        nullptr, nullptr);

    // 7. B' left half: d[k] * Mi[k][n] (indirect scaled transpose)
    k_bpl<<<dim3(DIMV / 32, NN / 64), 256>>>(R, inact, dv, Bph, Bpl);

    // 8. WT = W^T (bf16-domain transpose)
    k_tbf<<<dim3(NN / 64, NN / 64), 256>>>(Wh, Wl, NN, WTh, WTl, NN);

    // 9. A_rec = WT @ B'^T
    k_mma<1><<<dim3(16, 16), 256, SMG>>>(WTh, WTl, NN, Bph, Bpl, NN, NN,
                                         o_arec, NN, nullptr, nullptr, 0,
                                         nullptr, nullptr);

    // 10. D (full-row write) + mother_coefficients
    k_dfill<<<NN, 256>>>(o_fc, colmap, winv, dv, o_D);
    k_mc<<<DIMV, 256>>>(dv, o_mc);
}